// round 14
// baseline (speedup 1.0000x reference)
#include <cuda_runtime.h>
#include <cuda_fp16.h>
#include <math.h>

#define Bb 16
#define Hh 512
#define Ll 2048
#define Nn 64
#define NCH 32

typedef unsigned long long ull;
typedef unsigned short u16;
typedef unsigned int u32;

// ---------------- scratch (device globals; no allocations allowed) ----------
__device__ __align__(16) u16 d_g[(size_t)Bb * Hh * Ll];   // gelu output, fp16, [b][h][l]
__device__ __align__(16) u16 d_ow[Hh * Hh];               // out_weight fp16 [v][u]
__device__ __align__(16) u16 d_P[Hh * 128 * 64];   // P[m=128][j=64]
__device__ __align__(16) u16 d_M[Hh * 64 * 128];   // M[t=64][k=128]
__device__ __align__(16) u16 d_T[Hh * 64 * 64];    // T[t=64][j=64]
__device__ float2 d_A64[Hh * Nn];                  // A^64

// ---------------- PTX helpers ----------------------------------------------
__device__ __forceinline__ u32 smem_u32(const void* p) {
    u32 a; asm("{ .reg .u64 t; cvta.to.shared.u64 t, %1; cvt.u32.u64 %0, t; }" : "=r"(a) : "l"(p));
    return a;
}
__device__ __forceinline__ u32 h2u(__half2 h) {
    union { __half2 h; u32 u; } c; c.h = h; return c.u;
}
#define CP_ASYNC16(dst, src) asm volatile("cp.async.cg.shared.global [%0], [%1], 16;" :: "r"(dst), "l"(src) : "memory")
#define CP_COMMIT() asm volatile("cp.async.commit_group;" ::: "memory")
#define CP_WAIT(n)  asm volatile("cp.async.wait_group %0;" :: "n"(n) : "memory")

#define MMAF16(d, a, b) \
    asm volatile("mma.sync.aligned.m16n8k16.row.col.f32.f16.f16.f32 " \
        "{%0,%1,%2,%3}, {%4,%5,%6,%7}, {%8,%9}, {%0,%1,%2,%3};" \
        : "+f"((d)[0]), "+f"((d)[1]), "+f"((d)[2]), "+f"((d)[3]) \
        : "r"((a)[0]), "r"((a)[1]), "r"((a)[2]), "r"((a)[3]), "r"((b)[0]), "r"((b)[1]))

#define LDSM4(r0, r1, r2, r3, addr) \
    asm volatile("ldmatrix.sync.aligned.m8n8.x4.shared.b16 {%0,%1,%2,%3}, [%4];" \
        : "=r"(r0), "=r"(r1), "=r"(r2), "=r"(r3) : "r"(addr))

#define LDSM4T(r0, r1, r2, r3, addr) \
    asm volatile("ldmatrix.sync.aligned.m8n8.x4.trans.shared.b16 {%0,%1,%2,%3}, [%4];" \
        : "=r"(r0), "=r"(r1), "=r"(r2), "=r"(r3) : "r"(addr))

#define BARG(id) asm volatile("bar.sync %0, %1;" :: "r"(id), "r"(128) : "memory")

__device__ __forceinline__ u16 f2h(float x) {
    return __half_as_ushort(__float2half_rn(x));
}

// ---------------- kernel 1: fused prep + ow convert -------------------------
__global__ void prep_fused(const float* __restrict__ log_dt,
                           const float* __restrict__ Lambda,
                           const float* __restrict__ W,
                           const float* __restrict__ D,
                           const float* __restrict__ ow) {
    int h = blockIdx.x, t = threadIdx.x;
    __shared__ float zrs[64], zis[64], wkrs[64], wkis[64], kks[64];
    __shared__ __align__(16) u16 Ps[128 * 64];
    __shared__ __align__(16) u16 Ms[64 * 128];
    // ---- ow row h -> fp16 (coalesced) --------------------------------------
    {
        float4 v = ((const float4*)(ow + (size_t)h * Hh))[t];
        ushort4 o;
        o.x = f2h(v.x); o.y = f2h(v.y); o.z = f2h(v.z); o.w = f2h(v.w);
        *(ushort4*)&d_ow[(size_t)h * Hh + t * 4] = o;
    }
    if (t < 64) {
        int n = t;
        float dt_re = expf(log_dt[2 * h + 0]);
        float dt_im = expf(log_dt[2 * h + 1]);
        float lr = Lambda[2 * n + 0], li = Lambda[2 * n + 1];
        float zr = dt_re * lr, zi = dt_im * li;
        float sgn = (lr > 0.f) ? -1.f : 1.f;
        float nr = zr * sgn, ni = zi * sgn;
        float er = expf(nr);
        float num_re = er * cosf(ni) - 1.f;
        float num_im = er * sinf(ni);
        float eL = expf(nr * (float)Ll);
        float den_re = eL * cosf(ni * (float)Ll) - 1.f;
        float den_im = eL * sinf(ni * (float)Ll);
        float xr = den_re * lr - den_im * li;
        float xi = den_re * li + den_im * lr;
        float inv = 1.f / (xr * xr + xi * xi + 1e-7f);
        float rr = xr * inv, ri = -xi * inv;
        float wr0 = W[(h * Nn + n) * 2 + 0], wi0 = W[(h * Nn + n) * 2 + 1];
        float t1r = wr0 * num_re - wi0 * num_im;
        float t1i = wr0 * num_im + wi0 * num_re;
        zrs[n] = zr; zis[n] = zi;
        wkrs[n] = t1r * rr - t1i * ri;
        wkis[n] = t1r * ri + t1i * rr;
    }
    __syncthreads();
    // ---- phase A: per-n compute, fp16 into smem tiles ----------------------
    {
        int n = t & 63;
        int seg = t >> 6;
        int d0 = seg ? 33 : 0;
        int d1 = seg ? 65 : 33;
        float zr = zrs[n], zi = zis[n], wkr = wkrs[n], wki = wkis[n];
        for (int d = d0; d < d1; d++) {
            float df = (float)d;
            float e  = expf(zr * df);
            float cc = cosf(zi * df);
            float ss = sinf(zi * df);
            float Ar = e * cc, Ai = e * ss;
            float wr = wkr * Ar - wki * Ai;
            float wi = wkr * Ai + wki * Ar;
            if (d < 64) {
                int j = 63 - d;
                Ps[n * 64 + j]        = f2h(Ar);
                Ps[(64 + n) * 64 + j] = f2h(Ai);
            }
            if (d >= 1) {
                Ms[(d - 1) * 128 + n]      = f2h(wr);
                Ms[(d - 1) * 128 + 64 + n] = f2h(-wi);
            }
            if (d == 64) d_A64[h * Nn + n] = make_float2(Ar, Ai);
        }
    }
    // ---- phase B: kks[d] in fp32, same arithmetic/order --------------------
    if (t < 64) {
        float df = (float)t;
        float kk = 0.f;
        for (int n = 0; n < 64; n++) {
            float e  = expf(zrs[n] * df);
            float cc = cosf(zis[n] * df);
            float ss = sinf(zis[n] * df);
            float Ar = e * cc, Ai = e * ss;
            float wr = wkrs[n] * Ar - wkis[n] * Ai;
            kk += wr;
        }
        kks[t] = kk;
    }
    __syncthreads();
    // ---- phase C: coalesced bulk copies + T --------------------------------
    {
        const uint4* ps4 = (const uint4*)Ps;
        uint4* dp4 = (uint4*)(d_P + (size_t)h * 8192);
        const uint4* ms4 = (const uint4*)Ms;
        uint4* dm4 = (uint4*)(d_M + (size_t)h * 8192);
#pragma unroll
        for (int j = 0; j < 8; j++) {
            dp4[t + 128 * j] = ps4[t + 128 * j];
            dm4[t + 128 * j] = ms4[t + 128 * j];
        }
    }
    float Dh = D[h];
    for (int idx = t; idx < 4096; idx += 128) {
        int row = idx >> 6, col = idx & 63;
        float v = (col < row) ? kks[row - col] : ((col == row) ? (kks[0] + Dh) : 0.f);
        d_T[(h * 64 + row) * 64 + col] = f2h(v);
    }
}

// ---------------- kernel 2: chunked tensor-core scan (fp16, 4 groups) -------
// grid = 1024 (h x 2 halves); each CTA does 8 b; each group 2 b.
#define OP 0
#define OM 18432
#define OT 35840
#define OA64 45056
#define OGRP 45568
#define GU 0          /* Us: 32 chunks x 72 halfs = 4608 B */
#define GC 4608       /* Cs: 32 x 136 halfs = 8704 B */
#define GBA 13312     /* BA: 32 x 132 floats = 16896 B */
#define GYH 30208     /* Ys fp16: 32 x 72 halfs = 4608 B */
#define GST 34816     /* stage: 2048 floats = 8192 B */
#define GRPSZ 43008
#define SCAN_SMEM (OGRP + 4 * GRPSZ)   // 217600

__global__ void __launch_bounds__(512, 1)
scan2_kernel(const float* __restrict__ u) {
    extern __shared__ __align__(16) char sm[];
    const u32 sb = smem_u32(sm);
    const int t = threadIdx.x;
    const int wid = t >> 5, lane = t & 31;
    const int g = wid >> 2, wg = wid & 3, gtid = t & 127;
    const int qr = lane >> 2, qc = (lane & 3) * 2;
    const int lrow = lane & 15, lc8 = (lane >> 4) * 8;
    const int h = blockIdx.x >> 1;
    const int half = blockIdx.x & 1;
    const int barid = 1 + g;

    char* gb = sm + OGRP + g * GRPSZ;
    u16*   Us  = (u16*)(gb + GU);
    u16*   Cs  = (u16*)(gb + GC);
    float* BA  = (float*)(gb + GBA);
    u16*   Ysh = (u16*)(gb + GYH);
    float* Stg = (float*)(gb + GST);
    const u32 sbStg = sb + (u32)(OGRP + g * GRPSZ + GST);

    // ---- load per-h matrices + stage(it=0) into smem ----------------------
    for (int s = t; s < 1024; s += 512) {          // P: 128 rows x 8 segs
        int row = s >> 3, c = s & 7;
        CP_ASYNC16(sb + OP + (u32)(row * 144 + c * 16),
                   (const char*)(d_P + (size_t)(h * 128 + row) * 64 + c * 8));
    }
    for (int s = t; s < 1024; s += 512) {          // M: 64 rows x 16 segs
        int row = s >> 4, c = s & 15;
        CP_ASYNC16(sb + OM + (u32)(row * 272 + c * 16),
                   (const char*)(d_M + (size_t)(h * 64 + row) * 128 + c * 8));
    }
    for (int s = t; s < 512; s += 512) {           // T: 64 rows x 8 segs
        int row = s >> 3, c = s & 7;
        CP_ASYNC16(sb + OT + (u32)(row * 144 + c * 16),
                   (const char*)(d_T + (size_t)(h * 64 + row) * 64 + c * 8));
    }
    if (t < 32) CP_ASYNC16(sb + OA64 + t * 16, (const char*)(d_A64 + h * Nn) + t * 16);
    {   // stage u for it=0 of this group: b = half*8 + g*2
        const float* up0 = u + ((size_t)(half * 8 + g * 2) * Hh + h) * Ll;
#pragma unroll
        for (int j = 0; j < 4; j++) {
            int idx = gtid + 128 * j;
            CP_ASYNC16(sbStg + (u32)(idx * 16), (const char*)(up0 + idx * 4));
        }
    }
    CP_COMMIT(); CP_WAIT(0);
    __syncthreads();

    const u32 sbP = sb + OP;
    const u32 sbM = sb + OM;
    const u32 sbT = sb + OT;
    const float2* A64s = (const float2*)(sm + OA64);

    for (int it = 0; it < 2; it++) {
        int b = half * 8 + g * 2 + it;
        // ---- 1. convert stage -> Us fp16 (rows = chunk, stride 72) ---------
#pragma unroll
        for (int p = 0; p < 4; p++) {
            int i = gtid * 4 + p * 512;
            float4 v = *(const float4*)&Stg[i];
            __half2 p0 = __floats2half2_rn(v.x, v.y);
            __half2 p1 = __floats2half2_rn(v.z, v.w);
            *(uint2*)&Us[(i >> 6) * 72 + (i & 63)] = make_uint2(h2u(p0), h2u(p1));
        }
        BARG(barid);
        // ---- prefetch next iteration's u into stage ------------------------
        if (it == 0) {
            const float* upn = u + ((size_t)(b + 1) * Hh + h) * Ll;
#pragma unroll
            for (int j = 0; j < 4; j++) {
                int idx = gtid + 128 * j;
                CP_ASYNC16(sbStg + (u32)(idx * 16), (const char*)(upn + idx * 4));
            }
            CP_COMMIT();
        }
        // ---- 2. GEMM1: BA[128 x 32] = P @ U --------------------------------
        {
            float acc[2][4][4];
#pragma unroll
            for (int mt = 0; mt < 2; mt++)
#pragma unroll
                for (int nt = 0; nt < 4; nt++)
#pragma unroll
                    for (int i = 0; i < 4; i++) acc[mt][nt][i] = 0.f;
#pragma unroll
            for (int kk = 0; kk < 64; kk += 16) {
                u32 ah[2][4];
#pragma unroll
                for (int mt = 0; mt < 2; mt++) {
                    u32 ad = sbP + (u32)(((wg * 32 + mt * 16 + lrow) * 72 + kk + lc8) * 2);
                    LDSM4(ah[mt][0], ah[mt][1], ah[mt][2], ah[mt][3], ad);
                }
                u32 uh[4][2];
#pragma unroll
                for (int nt = 0; nt < 4; nt++) {
                    int o = (nt * 8 + qr) * 72 + kk + qc;
                    uh[nt][0] = *(const u32*)&Us[o];
                    uh[nt][1] = *(const u32*)&Us[o + 8];
                }
#pragma unroll
                for (int mt = 0; mt < 2; mt++)
#pragma unroll
                    for (int nt = 0; nt < 4; nt++)
                        MMAF16(acc[mt][nt], ah[mt], uh[nt]);
            }
#pragma unroll
            for (int mt = 0; mt < 2; mt++)
#pragma unroll
                for (int nt = 0; nt < 4; nt++)
#pragma unroll
                    for (int i = 0; i < 4; i++) {
                        int m = wg * 32 + mt * 16 + qr + ((i >= 2) ? 8 : 0);
                        int ch = nt * 8 + qc + (i & 1);
                        BA[ch * 132 + m] = acc[mt][nt][i];
                    }
        }
        BARG(barid);
        // ---- 3. carry scan (64 threads/group) ------------------------------
        if (gtid < 64) {
            int n = gtid;
            float2 a64 = A64s[n];
            float cr = 0.f, ci = 0.f;
#pragma unroll 4
            for (int ch = 0; ch < NCH; ch++) {
                Cs[ch * 136 + n]      = f2h(cr);
                Cs[ch * 136 + 64 + n] = f2h(ci);
                float br = BA[ch * 132 + n];
                float bi = BA[ch * 132 + 64 + n];
                float ncr = a64.x * cr - a64.y * ci + br;
                ci = a64.x * ci + a64.y * cr + bi;
                cr = ncr;
            }
        }
        BARG(barid);
        // ---- 4. GEMM2: Y = T @ U + M @ C; GELU on acc; store Ys fp16 -------
        {
            float acc[4][4];
#pragma unroll
            for (int nt = 0; nt < 4; nt++)
#pragma unroll
                for (int i = 0; i < 4; i++) acc[nt][i] = 0.f;
#pragma unroll
            for (int kk = 0; kk < 64; kk += 16) {
                u32 ah[4];
                u32 ad = sbT + (u32)(((wg * 16 + lrow) * 72 + kk + lc8) * 2);
                LDSM4(ah[0], ah[1], ah[2], ah[3], ad);
#pragma unroll
                for (int nt = 0; nt < 4; nt++) {
                    int ob = (nt * 8 + qr) * 72 + kk + qc;
                    u32 bh[2] = { *(const u32*)&Us[ob], *(const u32*)&Us[ob + 8] };
                    MMAF16(acc[nt], ah, bh);
                }
            }
#pragma unroll
            for (int kk = 0; kk < 128; kk += 16) {
                u32 ah[4];
                u32 ad = sbM + (u32)(((wg * 16 + lrow) * 136 + kk + lc8) * 2);
                LDSM4(ah[0], ah[1], ah[2], ah[3], ad);
#pragma unroll
                for (int nt = 0; nt < 4; nt++) {
                    int ob = (nt * 8 + qr) * 136 + kk + qc;
                    u32 bh[2] = { *(const u32*)&Cs[ob], *(const u32*)&Cs[ob + 8] };
                    MMAF16(acc[nt], ah, bh);
                }
            }
#pragma unroll
            for (int nt = 0; nt < 4; nt++)
#pragma unroll
                for (int i = 0; i < 4; i++) {
                    int tr = wg * 16 + qr + ((i >= 2) ? 8 : 0);
                    int ch = nt * 8 + qc + (i & 1);
                    float y = acc[nt][i];
                    float gg = 0.5f * y * (1.f + erff(y * 0.70710678118654752f));
                    Ysh[ch * 72 + tr] = f2h(gg);
                }
        }
        BARG(barid);
        // ---- 5. copy Ys fp16 -> gmem (coalesced 32B per thread) ------------
        {
            u16* gp = d_g + ((size_t)b * Hh + h) * Ll;
            int i = gtid * 16;
            int off = (i >> 6) * 72 + (i & 63);
            uint4 a0 = *(const uint4*)&Ysh[off];
            uint4 a1 = *(const uint4*)&Ysh[off + 8];
            *(uint4*)&gp[i] = a0;
            *(uint4*)&gp[i + 8] = a1;
        }
        if (it == 0) CP_WAIT(0);
        BARG(barid);
    }
}

// ---------------- kernel 3: HMMA fp16 GEMM, BK=64, 3-stage ------------------
#define BM 128
#define BN 128
#define BK 64
#define ASTR 72                     // u16 stride for A tiles (144 B rows)
#define AMATB (BM * ASTR * 2)       // 18432 B
#define BSTR 136                    // u16 stride for B tiles (272 B rows)
#define BMATB (BK * BSTR * 2)       // 17408 B
#define STAGEB (AMATB + BMATB)      // 35840
#define GEMM_SMEM (3 * STAGEB)      // 107520

__global__ void __launch_bounds__(256, 2)
gemm_hmma(const float* __restrict__ bias, float* __restrict__ out) {
    extern __shared__ __align__(16) char sm[];
    const u32 sb = smem_u32(sm);
    const int t = threadIdx.x;
    const int wid = t >> 5, lane = t & 31;
    const int warp_m = wid & 3, warp_n = wid >> 2;
    const int qr = lane >> 2, qc = (lane & 3) * 2;
    const int lrow = lane & 15, lc8 = (lane >> 4) * 8;
    const int b  = blockIdx.z;
    const int v0 = blockIdx.y * BM;
    const int l0 = blockIdx.x * BN;
    const int krow_l = (lane & 7) + ((lane >> 3) & 1) * 8;
    const int ncol_l = ((lane >> 4) & 1) * 8;

    float acc[2][8][4];
#pragma unroll
    for (int mt = 0; mt < 2; mt++)
#pragma unroll
        for (int nt = 0; nt < 8; nt++)
#pragma unroll
            for (int i = 0; i < 4; i++) acc[mt][nt][i] = 0.f;

    const int NK = Hh / BK;   // 8

    auto issue = [&](int c) {
        int k0 = c * BK;
        u32 st = sb + (u32)((c % 3) * STAGEB);
#pragma unroll
        for (int j = 0; j < 4; j++) {       // A: 1024 segs (128 rows x 8)
            int idx = t + 256 * j;
            int row = idx >> 3, seg = idx & 7;
            CP_ASYNC16(st + (u32)(row * (ASTR * 2) + seg * 16),
                       (const char*)(d_ow + (size_t)(v0 + row) * Hh + k0 + seg * 8));
        }
#pragma unroll
        for (int j = 0; j < 4; j++) {       // B: 1024 segs (64 rows x 16)
            int idx = t + 256 * j;
            int row = idx >> 4, seg = idx & 15;
            CP_ASYNC16(st + AMATB + (u32)(row * (BSTR * 2) + seg * 16),
                       (const char*)(d_g + ((size_t)b * Hh + k0 + row) * Ll + l0 + seg * 8));
        }
        CP_COMMIT();
    };

    issue(0);
    issue(1);
    for (int c = 0; c < NK; c++) {
        if (c + 2 < NK) { issue(c + 2); CP_WAIT(2); }
        else if (c + 1 < NK) { CP_WAIT(1); }
        else { CP_WAIT(0); }
        __syncthreads();

        u32 stg = sb + (u32)((c % 3) * STAGEB);
        u32 BHb = stg + AMATB;

#pragma unroll
        for (int kk = 0; kk < BK; kk += 16) {
            u32 ah[2][4];
#pragma unroll
            for (int mt = 0; mt < 2; mt++) {
                u32 ad = stg + (u32)(((warp_m * 32 + mt * 16 + lrow) * ASTR + kk + lc8) * 2);
                LDSM4(ah[mt][0], ah[mt][1], ah[mt][2], ah[mt][3], ad);
            }
            u32 bh[8][2];
#pragma unroll
            for (int p = 0; p < 4; p++) {
                u32 off = (u32)((kk + krow_l) * (BSTR * 2) +
                                (warp_n * 64 + p * 16 + ncol_l) * 2);
                LDSM4T(bh[2 * p][0], bh[2 * p][1], bh[2 * p + 1][0], bh[2 * p + 1][1], BHb + off);
            }
#pragma unroll
            for (int mt = 0; mt < 2; mt++)
#pragma unroll
                for (int nt = 0; nt < 8; nt++)
                    MMAF16(acc[mt][nt], ah[mt], bh[nt]);
        }
        __syncthreads();
    }

#pragma unroll
    for (int mt = 0; mt < 2; mt++) {
        int vg = v0 + warp_m * 32 + mt * 16 + qr;
        float bv0 = bias[vg];
        float bv1 = bias[vg + 8];
        float* r0 = out + (size_t)(b * Hh + vg) * Ll + l0 + warp_n * 64;
        float* r1 = r0 + 8 * Ll;
#pragma unroll
        for (int nt = 0; nt < 8; nt++) {
            int lg = nt * 8 + qc;
            *(float2*)(r0 + lg) = make_float2(acc[mt][nt][0] + bv0, acc[mt][nt][1] + bv0);
            *(float2*)(r1 + lg) = make_float2(acc[mt][nt][2] + bv1, acc[mt][nt][3] + bv1);
        }
    }
}

// ---------------- launch ----------------------------------------------------
extern "C" void kernel_launch(void* const* d_in, const int* in_sizes, int n_in,
                              void* d_out, int out_size) {
    const float* u          = (const float*)d_in[0];
    const float* log_dt     = (const float*)d_in[1];
    const float* Lambda     = (const float*)d_in[2];
    const float* W          = (const float*)d_in[3];
    const float* D          = (const float*)d_in[4];
    const float* out_weight = (const float*)d_in[5];
    const float* out_bias   = (const float*)d_in[6];
    float* out = (float*)d_out;

    cudaFuncSetAttribute(scan2_kernel, cudaFuncAttributeMaxDynamicSharedMemorySize, SCAN_SMEM);
    cudaFuncSetAttribute(gemm_hmma,   cudaFuncAttributeMaxDynamicSharedMemorySize, GEMM_SMEM);

    prep_fused<<<Hh, 128>>>(log_dt, Lambda, W, D, out_weight);
    scan2_kernel<<<Hh * 2, 512, SCAN_SMEM>>>(u);
    dim3 grid(Ll / BN, Hh / BM, Bb);
    gemm_hmma<<<grid, 256, GEMM_SMEM>>>(out_bias, out);
}

// round 15
// speedup vs baseline: 1.0469x; 1.0469x over previous
#include <cuda_runtime.h>
#include <cuda_fp16.h>
#include <math.h>

#define Bb 16
#define Hh 512
#define Ll 2048
#define Nn 64
#define NCH 32

typedef unsigned long long ull;
typedef unsigned short u16;
typedef unsigned int u32;

// ---------------- scratch (device globals; no allocations allowed) ----------
__device__ __align__(16) u16 d_g[(size_t)Bb * Hh * Ll];   // gelu output, fp16, [b][h][l]
__device__ __align__(16) u16 d_ow[Hh * Hh];               // out_weight fp16 [v][u]
__device__ __align__(16) u16 d_P[Hh * 128 * 64];   // P[m=128][j=64]
__device__ __align__(16) u16 d_M[Hh * 64 * 128];   // M[t=64][k=128]
__device__ __align__(16) u16 d_T[Hh * 64 * 64];    // T[t=64][j=64]
__device__ float2 d_A64[Hh * Nn];                  // A^64

// ---------------- PTX helpers ----------------------------------------------
__device__ __forceinline__ u32 smem_u32(const void* p) {
    u32 a; asm("{ .reg .u64 t; cvta.to.shared.u64 t, %1; cvt.u32.u64 %0, t; }" : "=r"(a) : "l"(p));
    return a;
}
__device__ __forceinline__ u32 h2u(__half2 h) {
    union { __half2 h; u32 u; } c; c.h = h; return c.u;
}
#define CP_ASYNC16(dst, src) asm volatile("cp.async.cg.shared.global [%0], [%1], 16;" :: "r"(dst), "l"(src) : "memory")
#define CP_COMMIT() asm volatile("cp.async.commit_group;" ::: "memory")
#define CP_WAIT(n)  asm volatile("cp.async.wait_group %0;" :: "n"(n) : "memory")

#define MMAF16(d, a, b) \
    asm volatile("mma.sync.aligned.m16n8k16.row.col.f32.f16.f16.f32 " \
        "{%0,%1,%2,%3}, {%4,%5,%6,%7}, {%8,%9}, {%0,%1,%2,%3};" \
        : "+f"((d)[0]), "+f"((d)[1]), "+f"((d)[2]), "+f"((d)[3]) \
        : "r"((a)[0]), "r"((a)[1]), "r"((a)[2]), "r"((a)[3]), "r"((b)[0]), "r"((b)[1]))

#define LDSM4(r0, r1, r2, r3, addr) \
    asm volatile("ldmatrix.sync.aligned.m8n8.x4.shared.b16 {%0,%1,%2,%3}, [%4];" \
        : "=r"(r0), "=r"(r1), "=r"(r2), "=r"(r3) : "r"(addr))

#define LDSM4T(r0, r1, r2, r3, addr) \
    asm volatile("ldmatrix.sync.aligned.m8n8.x4.trans.shared.b16 {%0,%1,%2,%3}, [%4];" \
        : "=r"(r0), "=r"(r1), "=r"(r2), "=r"(r3) : "r"(addr))

#define BARG(id) asm volatile("bar.sync %0, %1;" :: "r"(id), "r"(128) : "memory")

__device__ __forceinline__ u16 f2h(float x) {
    return __half_as_ushort(__float2half_rn(x));
}

// ---------------- kernel 1: fused prep + ow convert (fast intrinsics) -------
// dynamic smem layout (bytes):
#define PP_PS 0
#define PP_MS 16384
#define PP_WRS 32768            /* 64 rows x 65 floats (padded) = 16640 */
#define PP_SC 49408             /* zrs,zis,wkrs,wkis,kks: 5 x 256 */
#define PREP_SMEM 50688

__global__ void prep_fused(const float* __restrict__ log_dt,
                           const float* __restrict__ Lambda,
                           const float* __restrict__ W,
                           const float* __restrict__ D,
                           const float* __restrict__ ow) {
    extern __shared__ __align__(16) char psm[];
    u16* Ps = (u16*)(psm + PP_PS);
    u16* Ms = (u16*)(psm + PP_MS);
    float* WRS = (float*)(psm + PP_WRS);
    float* zrs  = (float*)(psm + PP_SC);
    float* zis  = zrs + 64;
    float* wkrs = zis + 64;
    float* wkis = wkrs + 64;
    float* kks  = wkis + 64;
    int h = blockIdx.x, t = threadIdx.x;
    // ---- ow row h -> fp16 (coalesced) --------------------------------------
    {
        float4 v = ((const float4*)(ow + (size_t)h * Hh))[t];
        ushort4 o;
        o.x = f2h(v.x); o.y = f2h(v.y); o.z = f2h(v.z); o.w = f2h(v.w);
        *(ushort4*)&d_ow[(size_t)h * Hh + t * 4] = o;
    }
    if (t < 64) {
        int n = t;
        float dt_re = __expf(log_dt[2 * h + 0]);
        float dt_im = __expf(log_dt[2 * h + 1]);
        float lr = Lambda[2 * n + 0], li = Lambda[2 * n + 1];
        float zr = dt_re * lr, zi = dt_im * li;
        float sgn = (lr > 0.f) ? -1.f : 1.f;
        float nr = zr * sgn, ni = zi * sgn;
        float er = __expf(nr);
        float cn, sn;
        __sincosf(ni, &sn, &cn);
        float num_re = er * cn - 1.f;
        float num_im = er * sn;
        float eL = __expf(nr * (float)Ll);
        float cL, sL;
        __sincosf(ni * (float)Ll, &sL, &cL);
        float den_re = eL * cL - 1.f;
        float den_im = eL * sL;
        float xr = den_re * lr - den_im * li;
        float xi = den_re * li + den_im * lr;
        float inv = 1.f / (xr * xr + xi * xi + 1e-7f);
        float rr = xr * inv, ri = -xi * inv;
        float wr0 = W[(h * Nn + n) * 2 + 0], wi0 = W[(h * Nn + n) * 2 + 1];
        float t1r = wr0 * num_re - wi0 * num_im;
        float t1i = wr0 * num_im + wi0 * num_re;
        zrs[n] = zr; zis[n] = zi;
        wkrs[n] = t1r * rr - t1i * ri;
        wkis[n] = t1r * ri + t1i * rr;
    }
    __syncthreads();
    // ---- phase A: per-n compute, fp16 into smem tiles + fp32 wr ------------
    {
        int n = t & 63;
        int seg = t >> 6;
        int d0 = seg ? 33 : 0;
        int d1 = seg ? 65 : 33;
        float zr = zrs[n], zi = zis[n], wkr = wkrs[n], wki = wkis[n];
        for (int d = d0; d < d1; d++) {
            float df = (float)d;
            float e = __expf(zr * df);
            float cc, ss;
            __sincosf(zi * df, &ss, &cc);
            float Ar = e * cc, Ai = e * ss;
            float wr = wkr * Ar - wki * Ai;
            float wi = wkr * Ai + wki * Ar;
            if (d < 64) {
                int j = 63 - d;
                Ps[n * 64 + j]        = f2h(Ar);
                Ps[(64 + n) * 64 + j] = f2h(Ai);
                WRS[d * 65 + n] = wr;
            }
            if (d >= 1) {
                Ms[(d - 1) * 128 + n]      = f2h(wr);
                Ms[(d - 1) * 128 + 64 + n] = f2h(-wi);
            }
            if (d == 64) d_A64[h * Nn + n] = make_float2(Ar, Ai);
        }
    }
    __syncthreads();
    // ---- phase B: kks[d] = sum_n WRS[d][n] (fp32, n-ascending) -------------
    if (t < 64) {
        float kk = 0.f;
        const float* wp = WRS + t * 65;
        for (int n = 0; n < 64; n++) kk += wp[n];
        kks[t] = kk;
    }
    __syncthreads();
    // ---- phase C: coalesced bulk copies + T --------------------------------
    {
        const uint4* ps4 = (const uint4*)Ps;
        uint4* dp4 = (uint4*)(d_P + (size_t)h * 8192);
        const uint4* ms4 = (const uint4*)Ms;
        uint4* dm4 = (uint4*)(d_M + (size_t)h * 8192);
#pragma unroll
        for (int j = 0; j < 8; j++) {
            dp4[t + 128 * j] = ps4[t + 128 * j];
            dm4[t + 128 * j] = ms4[t + 128 * j];
        }
    }
    float Dh = D[h];
    for (int idx = t; idx < 4096; idx += 128) {
        int row = idx >> 6, col = idx & 63;
        float v = (col < row) ? kks[row - col] : ((col == row) ? (kks[0] + Dh) : 0.f);
        d_T[(h * 64 + row) * 64 + col] = f2h(v);
    }
}

// ---------------- kernel 2: chunked tensor-core scan (fp16, 4 groups) -------
// grid = 1024 (h x 2 halves); each CTA does 8 b; each group 2 b.
#define OP 0
#define OM 18432
#define OT 35840
#define OA64 45056
#define OGRP 45568
#define GU 0          /* Us: 32 chunks x 72 halfs = 4608 B */
#define GC 4608       /* Cs: 32 x 136 halfs = 8704 B */
#define GBA 13312     /* BA: 32 x 132 floats = 16896 B */
#define GYH 30208     /* Ys fp16: 32 x 72 halfs = 4608 B */
#define GST 34816     /* stage: 2048 floats = 8192 B */
#define GRPSZ 43008
#define SCAN_SMEM (OGRP + 4 * GRPSZ)   // 217600

__global__ void __launch_bounds__(512, 1)
scan2_kernel(const float* __restrict__ u) {
    extern __shared__ __align__(16) char sm[];
    const u32 sb = smem_u32(sm);
    const int t = threadIdx.x;
    const int wid = t >> 5, lane = t & 31;
    const int g = wid >> 2, wg = wid & 3, gtid = t & 127;
    const int qr = lane >> 2, qc = (lane & 3) * 2;
    const int lrow = lane & 15, lc8 = (lane >> 4) * 8;
    const int h = blockIdx.x >> 1;
    const int half = blockIdx.x & 1;
    const int barid = 1 + g;

    char* gb = sm + OGRP + g * GRPSZ;
    u16*   Us  = (u16*)(gb + GU);
    u16*   Cs  = (u16*)(gb + GC);
    float* BA  = (float*)(gb + GBA);
    u16*   Ysh = (u16*)(gb + GYH);
    float* Stg = (float*)(gb + GST);
    const u32 sbStg = sb + (u32)(OGRP + g * GRPSZ + GST);

    // ---- load per-h matrices + stage(it=0) into smem ----------------------
    for (int s = t; s < 1024; s += 512) {          // P: 128 rows x 8 segs
        int row = s >> 3, c = s & 7;
        CP_ASYNC16(sb + OP + (u32)(row * 144 + c * 16),
                   (const char*)(d_P + (size_t)(h * 128 + row) * 64 + c * 8));
    }
    for (int s = t; s < 1024; s += 512) {          // M: 64 rows x 16 segs
        int row = s >> 4, c = s & 15;
        CP_ASYNC16(sb + OM + (u32)(row * 272 + c * 16),
                   (const char*)(d_M + (size_t)(h * 64 + row) * 128 + c * 8));
    }
    for (int s = t; s < 512; s += 512) {           // T: 64 rows x 8 segs
        int row = s >> 3, c = s & 7;
        CP_ASYNC16(sb + OT + (u32)(row * 144 + c * 16),
                   (const char*)(d_T + (size_t)(h * 64 + row) * 64 + c * 8));
    }
    if (t < 32) CP_ASYNC16(sb + OA64 + t * 16, (const char*)(d_A64 + h * Nn) + t * 16);
    {   // stage u for it=0 of this group: b = half*8 + g*2
        const float* up0 = u + ((size_t)(half * 8 + g * 2) * Hh + h) * Ll;
#pragma unroll
        for (int j = 0; j < 4; j++) {
            int idx = gtid + 128 * j;
            CP_ASYNC16(sbStg + (u32)(idx * 16), (const char*)(up0 + idx * 4));
        }
    }
    CP_COMMIT(); CP_WAIT(0);
    __syncthreads();

    const u32 sbP = sb + OP;
    const u32 sbM = sb + OM;
    const u32 sbT = sb + OT;
    const float2* A64s = (const float2*)(sm + OA64);

    for (int it = 0; it < 2; it++) {
        int b = half * 8 + g * 2 + it;
        // ---- 1. convert stage -> Us fp16 (rows = chunk, stride 72) ---------
#pragma unroll
        for (int p = 0; p < 4; p++) {
            int i = gtid * 4 + p * 512;
            float4 v = *(const float4*)&Stg[i];
            __half2 p0 = __floats2half2_rn(v.x, v.y);
            __half2 p1 = __floats2half2_rn(v.z, v.w);
            *(uint2*)&Us[(i >> 6) * 72 + (i & 63)] = make_uint2(h2u(p0), h2u(p1));
        }
        BARG(barid);
        // ---- prefetch next iteration's u into stage ------------------------
        if (it == 0) {
            const float* upn = u + ((size_t)(b + 1) * Hh + h) * Ll;
#pragma unroll
            for (int j = 0; j < 4; j++) {
                int idx = gtid + 128 * j;
                CP_ASYNC16(sbStg + (u32)(idx * 16), (const char*)(upn + idx * 4));
            }
            CP_COMMIT();
        }
        // ---- 2. GEMM1: BA[128 x 32] = P @ U --------------------------------
        {
            float acc[2][4][4];
#pragma unroll
            for (int mt = 0; mt < 2; mt++)
#pragma unroll
                for (int nt = 0; nt < 4; nt++)
#pragma unroll
                    for (int i = 0; i < 4; i++) acc[mt][nt][i] = 0.f;
#pragma unroll
            for (int kk = 0; kk < 64; kk += 16) {
                u32 ah[2][4];
#pragma unroll
                for (int mt = 0; mt < 2; mt++) {
                    u32 ad = sbP + (u32)(((wg * 32 + mt * 16 + lrow) * 72 + kk + lc8) * 2);
                    LDSM4(ah[mt][0], ah[mt][1], ah[mt][2], ah[mt][3], ad);
                }
                u32 uh[4][2];
#pragma unroll
                for (int nt = 0; nt < 4; nt++) {
                    int o = (nt * 8 + qr) * 72 + kk + qc;
                    uh[nt][0] = *(const u32*)&Us[o];
                    uh[nt][1] = *(const u32*)&Us[o + 8];
                }
#pragma unroll
                for (int mt = 0; mt < 2; mt++)
#pragma unroll
                    for (int nt = 0; nt < 4; nt++)
                        MMAF16(acc[mt][nt], ah[mt], uh[nt]);
            }
#pragma unroll
            for (int mt = 0; mt < 2; mt++)
#pragma unroll
                for (int nt = 0; nt < 4; nt++)
#pragma unroll
                    for (int i = 0; i < 4; i++) {
                        int m = wg * 32 + mt * 16 + qr + ((i >= 2) ? 8 : 0);
                        int ch = nt * 8 + qc + (i & 1);
                        BA[ch * 132 + m] = acc[mt][nt][i];
                    }
        }
        BARG(barid);
        // ---- 3. carry scan (64 threads/group) ------------------------------
        if (gtid < 64) {
            int n = gtid;
            float2 a64 = A64s[n];
            float cr = 0.f, ci = 0.f;
#pragma unroll 4
            for (int ch = 0; ch < NCH; ch++) {
                Cs[ch * 136 + n]      = f2h(cr);
                Cs[ch * 136 + 64 + n] = f2h(ci);
                float br = BA[ch * 132 + n];
                float bi = BA[ch * 132 + 64 + n];
                float ncr = a64.x * cr - a64.y * ci + br;
                ci = a64.x * ci + a64.y * cr + bi;
                cr = ncr;
            }
        }
        BARG(barid);
        // ---- 4. GEMM2: Y = T @ U + M @ C; GELU on acc; store Ys fp16 -------
        {
            float acc[4][4];
#pragma unroll
            for (int nt = 0; nt < 4; nt++)
#pragma unroll
                for (int i = 0; i < 4; i++) acc[nt][i] = 0.f;
#pragma unroll
            for (int kk = 0; kk < 64; kk += 16) {
                u32 ah[4];
                u32 ad = sbT + (u32)(((wg * 16 + lrow) * 72 + kk + lc8) * 2);
                LDSM4(ah[0], ah[1], ah[2], ah[3], ad);
#pragma unroll
                for (int nt = 0; nt < 4; nt++) {
                    int ob = (nt * 8 + qr) * 72 + kk + qc;
                    u32 bh[2] = { *(const u32*)&Us[ob], *(const u32*)&Us[ob + 8] };
                    MMAF16(acc[nt], ah, bh);
                }
            }
#pragma unroll
            for (int kk = 0; kk < 128; kk += 16) {
                u32 ah[4];
                u32 ad = sbM + (u32)(((wg * 16 + lrow) * 136 + kk + lc8) * 2);
                LDSM4(ah[0], ah[1], ah[2], ah[3], ad);
#pragma unroll
                for (int nt = 0; nt < 4; nt++) {
                    int ob = (nt * 8 + qr) * 136 + kk + qc;
                    u32 bh[2] = { *(const u32*)&Cs[ob], *(const u32*)&Cs[ob + 8] };
                    MMAF16(acc[nt], ah, bh);
                }
            }
#pragma unroll
            for (int nt = 0; nt < 4; nt++)
#pragma unroll
                for (int i = 0; i < 4; i++) {
                    int tr = wg * 16 + qr + ((i >= 2) ? 8 : 0);
                    int ch = nt * 8 + qc + (i & 1);
                    float y = acc[nt][i];
                    float gg = 0.5f * y * (1.f + erff(y * 0.70710678118654752f));
                    Ysh[ch * 72 + tr] = f2h(gg);
                }
        }
        BARG(barid);
        // ---- 5. copy Ys fp16 -> gmem (coalesced 32B per thread) ------------
        {
            u16* gp = d_g + ((size_t)b * Hh + h) * Ll;
            int i = gtid * 16;
            int off = (i >> 6) * 72 + (i & 63);
            uint4 a0 = *(const uint4*)&Ysh[off];
            uint4 a1 = *(const uint4*)&Ysh[off + 8];
            *(uint4*)&gp[i] = a0;
            *(uint4*)&gp[i + 8] = a1;
        }
        if (it == 0) CP_WAIT(0);
        BARG(barid);
    }
}

// ---------------- kernel 3: HMMA fp16 GEMM, BK=64, 3-stage ------------------
#define BM 128
#define BN 128
#define BK 64
#define ASTR 72                     // u16 stride for A tiles (144 B rows)
#define AMATB (BM * ASTR * 2)       // 18432 B
#define BSTR 136                    // u16 stride for B tiles (272 B rows)
#define BMATB (BK * BSTR * 2)       // 17408 B
#define STAGEB (AMATB + BMATB)      // 35840
#define GEMM_SMEM (3 * STAGEB)      // 107520

__global__ void __launch_bounds__(256, 2)
gemm_hmma(const float* __restrict__ bias, float* __restrict__ out) {
    extern __shared__ __align__(16) char sm[];
    const u32 sb = smem_u32(sm);
    const int t = threadIdx.x;
    const int wid = t >> 5, lane = t & 31;
    const int warp_m = wid & 3, warp_n = wid >> 2;
    const int qr = lane >> 2, qc = (lane & 3) * 2;
    const int lrow = lane & 15, lc8 = (lane >> 4) * 8;
    const int b  = blockIdx.z;
    const int v0 = blockIdx.y * BM;
    const int l0 = blockIdx.x * BN;
    const int krow_l = (lane & 7) + ((lane >> 3) & 1) * 8;
    const int ncol_l = ((lane >> 4) & 1) * 8;

    float acc[2][8][4];
#pragma unroll
    for (int mt = 0; mt < 2; mt++)
#pragma unroll
        for (int nt = 0; nt < 8; nt++)
#pragma unroll
            for (int i = 0; i < 4; i++) acc[mt][nt][i] = 0.f;

    const int NK = Hh / BK;   // 8

    auto issue = [&](int c) {
        int k0 = c * BK;
        u32 st = sb + (u32)((c % 3) * STAGEB);
#pragma unroll
        for (int j = 0; j < 4; j++) {       // A: 1024 segs (128 rows x 8)
            int idx = t + 256 * j;
            int row = idx >> 3, seg = idx & 7;
            CP_ASYNC16(st + (u32)(row * (ASTR * 2) + seg * 16),
                       (const char*)(d_ow + (size_t)(v0 + row) * Hh + k0 + seg * 8));
        }
#pragma unroll
        for (int j = 0; j < 4; j++) {       // B: 1024 segs (64 rows x 16)
            int idx = t + 256 * j;
            int row = idx >> 4, seg = idx & 15;
            CP_ASYNC16(st + AMATB + (u32)(row * (BSTR * 2) + seg * 16),
                       (const char*)(d_g + ((size_t)b * Hh + k0 + row) * Ll + l0 + seg * 8));
        }
        CP_COMMIT();
    };

    issue(0);
    issue(1);
    for (int c = 0; c < NK; c++) {
        if (c + 2 < NK) { issue(c + 2); CP_WAIT(2); }
        else if (c + 1 < NK) { CP_WAIT(1); }
        else { CP_WAIT(0); }
        __syncthreads();

        u32 stg = sb + (u32)((c % 3) * STAGEB);
        u32 BHb = stg + AMATB;

#pragma unroll
        for (int kk = 0; kk < BK; kk += 16) {
            u32 ah[2][4];
#pragma unroll
            for (int mt = 0; mt < 2; mt++) {
                u32 ad = stg + (u32)(((warp_m * 32 + mt * 16 + lrow) * ASTR + kk + lc8) * 2);
                LDSM4(ah[mt][0], ah[mt][1], ah[mt][2], ah[mt][3], ad);
            }
            u32 bh[8][2];
#pragma unroll
            for (int p = 0; p < 4; p++) {
                u32 off = (u32)((kk + krow_l) * (BSTR * 2) +
                                (warp_n * 64 + p * 16 + ncol_l) * 2);
                LDSM4T(bh[2 * p][0], bh[2 * p][1], bh[2 * p + 1][0], bh[2 * p + 1][1], BHb + off);
            }
#pragma unroll
            for (int mt = 0; mt < 2; mt++)
#pragma unroll
                for (int nt = 0; nt < 8; nt++)
                    MMAF16(acc[mt][nt], ah[mt], bh[nt]);
        }
        __syncthreads();
    }

#pragma unroll
    for (int mt = 0; mt < 2; mt++) {
        int vg = v0 + warp_m * 32 + mt * 16 + qr;
        float bv0 = bias[vg];
        float bv1 = bias[vg + 8];
        float* r0 = out + (size_t)(b * Hh + vg) * Ll + l0 + warp_n * 64;
        float* r1 = r0 + 8 * Ll;
#pragma unroll
        for (int nt = 0; nt < 8; nt++) {
            int lg = nt * 8 + qc;
            *(float2*)(r0 + lg) = make_float2(acc[mt][nt][0] + bv0, acc[mt][nt][1] + bv0);
            *(float2*)(r1 + lg) = make_float2(acc[mt][nt][2] + bv1, acc[mt][nt][3] + bv1);
        }
    }
}

// ---------------- launch ----------------------------------------------------
extern "C" void kernel_launch(void* const* d_in, const int* in_sizes, int n_in,
                              void* d_out, int out_size) {
    const float* u          = (const float*)d_in[0];
    const float* log_dt     = (const float*)d_in[1];
    const float* Lambda     = (const float*)d_in[2];
    const float* W          = (const float*)d_in[3];
    const float* D          = (const float*)d_in[4];
    const float* out_weight = (const float*)d_in[5];
    const float* out_bias   = (const float*)d_in[6];
    float* out = (float*)d_out;

    cudaFuncSetAttribute(prep_fused,   cudaFuncAttributeMaxDynamicSharedMemorySize, PREP_SMEM);
    cudaFuncSetAttribute(scan2_kernel, cudaFuncAttributeMaxDynamicSharedMemorySize, SCAN_SMEM);
    cudaFuncSetAttribute(gemm_hmma,    cudaFuncAttributeMaxDynamicSharedMemorySize, GEMM_SMEM);

    prep_fused<<<Hh, 128, PREP_SMEM>>>(log_dt, Lambda, W, D, out_weight);
    scan2_kernel<<<Hh * 2, 512, SCAN_SMEM>>>(u);
    dim3 grid(Ll / BN, Hh / BM, Bb);
    gemm_hmma<<<grid, 256, GEMM_SMEM>>>(out_bias, out);
}